// round 15
// baseline (speedup 1.0000x reference)
#include <cuda_runtime.h>
#include <math.h>
#include <stdint.h>

#define BB 8
#define NN 2048
#define FIN 256
#define FOUT 128
#define ALPHA 0.2f
#define CUTOFF 0.1f
#define NEGINF -9e15f

#define MT 128          // queries per CTA (attn)
#define KT 64           // keys per tile
#define HROW 272        // H/W smem row stride bytes (136 bf16): LDSM conflict-free
#define XROW 80         // x smem row stride bytes (40 bf16): LDSM conflict-free

// Scratch (no cudaMalloc allowed)
__device__ uint16_t g_hb_hi[BB * NN * FOUT];   // h bf16 hi
__device__ uint16_t g_hb_lo[BB * NN * FOUT];   // h bf16 residual
__device__ uint16_t g_wb_hi[FIN * FOUT];       // W bf16 hi
__device__ uint16_t g_wb_lo[FIN * FOUT];       // W bf16 residual
__device__ float g_fs[BB * NN];
__device__ float g_fd[BB * NN];
__device__ float g_fdmax[BB];

// ---------------------------------------------------------------------------
// helpers
// ---------------------------------------------------------------------------
__device__ __forceinline__ uint32_t smem_u32(const void* p) {
    uint32_t a;
    asm("{ .reg .u64 t; cvta.to.shared.u64 t, %1; cvt.u32.u64 %0, t; }"
        : "=r"(a) : "l"(p));
    return a;
}
// pack two f32 -> bf16x2 (lo half = pe, hi half = po)
__device__ __forceinline__ uint32_t bfpack(float po, float pe) {
    uint32_t r;
    asm("cvt.rn.bf16x2.f32 %0, %1, %2;" : "=r"(r) : "f"(po), "f"(pe));
    return r;
}
#define MMA_BF16(d, a, b0, b1)                                                  \
    asm volatile("mma.sync.aligned.m16n8k16.row.col.f32.bf16.bf16.f32 "         \
                 "{%0,%1,%2,%3},{%4,%5,%6,%7},{%8,%9},{%0,%1,%2,%3};"           \
                 : "+f"((d)[0]), "+f"((d)[1]), "+f"((d)[2]), "+f"((d)[3])       \
                 : "r"((a)[0]), "r"((a)[1]), "r"((a)[2]), "r"((a)[3]),          \
                   "r"(b0), "r"(b1))
#define LDSM4(r0, r1, r2, r3, addr)                                             \
    asm volatile("ldmatrix.sync.aligned.m8n8.x4.shared.b16 "                    \
                 "{%0,%1,%2,%3}, [%4];"                                         \
                 : "=r"(r0), "=r"(r1), "=r"(r2), "=r"(r3) : "r"(addr))
#define LDSM4T(r0, r1, r2, r3, addr)                                            \
    asm volatile("ldmatrix.sync.aligned.m8n8.x4.trans.shared.b16 "              \
                 "{%0,%1,%2,%3}, [%4];"                                         \
                 : "=r"(r0), "=r"(r1), "=r"(r2), "=r"(r3) : "r"(addr))
#define CP16(dst, src) \
    asm volatile("cp.async.cg.shared.global [%0], [%1], 16;" :: "r"(dst), "l"(src))
#define CP4(dst, src) \
    asm volatile("cp.async.ca.shared.global [%0], [%1], 4;" :: "r"(dst), "l"(src))
#define CP_COMMIT() asm volatile("cp.async.commit_group;" ::: "memory")
#define CP_WAIT(n)  asm volatile("cp.async.wait_group %0;" :: "n"(n) : "memory")

// ---------------------------------------------------------------------------
// Kernel 0: split W into bf16 hi/lo (once; W reused by all gemm CTAs)
// ---------------------------------------------------------------------------
__global__ void wsplit_kernel(const float* __restrict__ W) {
    int i = blockIdx.x * 256 + threadIdx.x;          // pair index, 16384 total
    float2 v = ((const float2*)W)[i];
    uint32_t hi = bfpack(v.y, v.x);
    float r0 = v.x - __uint_as_float(hi << 16);
    float r1 = v.y - __uint_as_float(hi & 0xffff0000u);
    ((uint32_t*)g_wb_hi)[i] = hi;
    ((uint32_t*)g_wb_lo)[i] = bfpack(r1, r0);
}

// ---------------------------------------------------------------------------
// Kernel 1: h = x @ W via bf16 split-split MMA (3 products).
// 64 rows/CTA, 256 threads, 8 warps: warp w -> rows (w&3)*16, n-half (w>>2)*64.
// Epilogue: store h bf16 hi/lo + fs/fd partial dots.
// ---------------------------------------------------------------------------
#define GO_XHI 0
#define GO_XLO 5120
#define GO_W   10240            /* per buf: hi 8704 + lo 8704 = 17408; x2 */
#define GO_PS  45056
#define GO_PD  45568
#define GO_TOT 46080

__global__ __launch_bounds__(256, 2)
void gemm_h_kernel(const float* __restrict__ x, const float* __restrict__ a) {
    __shared__ char sm[GO_TOT];
    const uint32_t sb = smem_u32(sm);

    const int t   = threadIdx.x;
    const int lid = t & 31;
    const int w   = t >> 5;
    const int g   = lid >> 2;
    const int t4  = lid & 3;
    const int row0 = blockIdx.x * 64;
    const int wr  = (w & 3) * 16;        // warp row base (local)
    const int nh  = (w >> 2) * 64;       // warp n-half base

    // prefetch W chunk 0
    {
#pragma unroll
        for (int e = 0; e < 4; e++) {
            int idx = t + e * 256;           // 0..1023
            int hl = idx >> 9, rem = idx & 511;
            int r = rem >> 4, c = rem & 15;
            const char* src = (const char*)(hl ? g_wb_lo : g_wb_hi) +
                              (size_t)r * 256 + c * 16;
            CP16(sb + GO_W + hl * 8704 + (uint32_t)(r * HROW + c * 16), src);
        }
        CP_COMMIT();
    }

    float acc[8][4];
#pragma unroll
    for (int nt = 0; nt < 8; nt++)
#pragma unroll
        for (int c = 0; c < 4; c++) acc[nt][c] = 0.f;

    for (int ch = 0; ch < 8; ch++) {
        const int k0 = ch * 32;
        const int buf = ch & 1;

        // LDG x chunk -> registers (row = t>>2, 8 floats at (t&3)*8)
        const int xr = t >> 2, xc = (t & 3) * 8;
        float4 xv0 = ((const float4*)(x + (size_t)(row0 + xr) * FIN + k0 + xc))[0];
        float4 xv1 = ((const float4*)(x + (size_t)(row0 + xr) * FIN + k0 + xc))[1];

        // prefetch next W chunk
        if (ch + 1 < 8) {
#pragma unroll
            for (int e = 0; e < 4; e++) {
                int idx = t + e * 256;
                int hl = idx >> 9, rem = idx & 511;
                int r = rem >> 4, c = rem & 15;
                const char* src = (const char*)(hl ? g_wb_lo : g_wb_hi) +
                                  (size_t)(ch + 1) * 32 * 256 + (size_t)r * 256 + c * 16;
                CP16(sb + GO_W + (buf ^ 1) * 17408 + hl * 8704 +
                     (uint32_t)(r * HROW + c * 16), src);
            }
            CP_COMMIT();
        }

        // split x -> bf16 hi/lo smem
        {
            uint32_t h0 = bfpack(xv0.y, xv0.x), h1 = bfpack(xv0.w, xv0.z);
            uint32_t h2 = bfpack(xv1.y, xv1.x), h3 = bfpack(xv1.w, xv1.z);
            float r0 = xv0.x - __uint_as_float(h0 << 16);
            float r1 = xv0.y - __uint_as_float(h0 & 0xffff0000u);
            float r2 = xv0.z - __uint_as_float(h1 << 16);
            float r3 = xv0.w - __uint_as_float(h1 & 0xffff0000u);
            float r4 = xv1.x - __uint_as_float(h2 << 16);
            float r5 = xv1.y - __uint_as_float(h2 & 0xffff0000u);
            float r6 = xv1.z - __uint_as_float(h3 << 16);
            float r7 = xv1.w - __uint_as_float(h3 & 0xffff0000u);
            uint32_t off = (uint32_t)(xr * XROW + (t & 3) * 16);
            *(uint4*)(sm + GO_XHI + off) = make_uint4(h0, h1, h2, h3);
            *(uint4*)(sm + GO_XLO + off) =
                make_uint4(bfpack(r1, r0), bfpack(r3, r2),
                           bfpack(r5, r4), bfpack(r7, r6));
        }
        if (ch + 1 < 8) { CP_WAIT(1); } else { CP_WAIT(0); }
        __syncthreads();

        // MMA sweep
        const uint32_t xb = sb + (uint32_t)(wr * XROW) +
                            (uint32_t)((lid & 15) * XROW + (lid >> 4) * 16);
        const uint32_t wbh = sb + GO_W + buf * 17408;
#pragma unroll
        for (int kc = 0; kc < 2; kc++) {
            uint32_t ahi[4], alo[4];
            LDSM4(ahi[0], ahi[1], ahi[2], ahi[3], xb + GO_XHI + kc * 32);
            LDSM4(alo[0], alo[1], alo[2], alo[3], xb + GO_XLO + kc * 32);
            uint32_t bbase = wbh + (uint32_t)(kc * 16 * HROW) +
                             (uint32_t)((lid & 15) * HROW + (lid >> 4) * 16);
#pragma unroll
            for (int ntp = 0; ntp < 4; ntp++) {
                uint32_t boff = bbase + (uint32_t)((nh + ntp * 16) * 2);
                uint32_t bh0, bh1, bh2, bh3, bl0, bl1, bl2, bl3;
                LDSM4T(bh0, bh1, bh2, bh3, boff);
                LDSM4T(bl0, bl1, bl2, bl3, boff + 8704);
                MMA_BF16(acc[2 * ntp],     ahi, bh0, bh1);
                MMA_BF16(acc[2 * ntp],     ahi, bl0, bl1);
                MMA_BF16(acc[2 * ntp],     alo, bh0, bh1);
                MMA_BF16(acc[2 * ntp + 1], ahi, bh2, bh3);
                MMA_BF16(acc[2 * ntp + 1], ahi, bl2, bl3);
                MMA_BF16(acc[2 * ntp + 1], alo, bh2, bh3);
            }
        }
        __syncthreads();   // before x smem overwrite
    }

    // ---- epilogue: store h bf16 hi/lo; fs/fd partial dots ----
    const int rowA = row0 + wr + g;
    const int rowB = rowA + 8;
    float psA = 0.f, pdA = 0.f, psB = 0.f, pdB = 0.f;
#pragma unroll
    for (int nt = 0; nt < 8; nt++) {
        int col = nh + nt * 8 + 2 * t4;
        float c0 = acc[nt][0], c1 = acc[nt][1];
        float c2 = acc[nt][2], c3 = acc[nt][3];
        uint32_t hA = bfpack(c1, c0);
        uint32_t hB = bfpack(c3, c2);
        float rA0 = c0 - __uint_as_float(hA << 16);
        float rA1 = c1 - __uint_as_float(hA & 0xffff0000u);
        float rB0 = c2 - __uint_as_float(hB << 16);
        float rB1 = c3 - __uint_as_float(hB & 0xffff0000u);
        *(uint32_t*)(g_hb_hi + (size_t)rowA * FOUT + col) = hA;
        *(uint32_t*)(g_hb_hi + (size_t)rowB * FOUT + col) = hB;
        *(uint32_t*)(g_hb_lo + (size_t)rowA * FOUT + col) = bfpack(rA1, rA0);
        *(uint32_t*)(g_hb_lo + (size_t)rowB * FOUT + col) = bfpack(rB1, rB0);
        float a0s = __ldg(a + col), a1s = __ldg(a + col + 1);
        float a0d = __ldg(a + FOUT + col), a1d = __ldg(a + FOUT + col + 1);
        psA += c0 * a0s + c1 * a1s;  pdA += c0 * a0d + c1 * a1d;
        psB += c2 * a0s + c3 * a1s;  pdB += c2 * a0d + c3 * a1d;
    }
    psA += __shfl_xor_sync(0xffffffffu, psA, 1);
    psA += __shfl_xor_sync(0xffffffffu, psA, 2);
    pdA += __shfl_xor_sync(0xffffffffu, pdA, 1);
    pdA += __shfl_xor_sync(0xffffffffu, pdA, 2);
    psB += __shfl_xor_sync(0xffffffffu, psB, 1);
    psB += __shfl_xor_sync(0xffffffffu, psB, 2);
    pdB += __shfl_xor_sync(0xffffffffu, pdB, 1);
    pdB += __shfl_xor_sync(0xffffffffu, pdB, 2);
    float* ps = (float*)(sm + GO_PS);
    float* pd = (float*)(sm + GO_PD);
    if (t4 == 0) {
        int half = w >> 2;
        ps[(wr + g) * 2 + half]     = psA;
        ps[(wr + g + 8) * 2 + half] = psB;
        pd[(wr + g) * 2 + half]     = pdA;
        pd[(wr + g + 8) * 2 + half] = pdB;
    }
    __syncthreads();
    if (t < 64) {
        g_fs[row0 + t] = ps[t * 2] + ps[t * 2 + 1];
        g_fd[row0 + t] = pd[t * 2] + pd[t * 2 + 1];
    }
}

// ---------------------------------------------------------------------------
// Kernel 1b: per-batch max of f_dst
// ---------------------------------------------------------------------------
__global__ void fdmax_kernel() {
    __shared__ float red[8];
    const int b = blockIdx.x;
    const int t = threadIdx.x;
    float m = -INFINITY;
    for (int j = t; j < NN; j += 256) m = fmaxf(m, g_fd[b * NN + j]);
#pragma unroll
    for (int o = 16; o > 0; o >>= 1)
        m = fmaxf(m, __shfl_xor_sync(0xffffffffu, m, o));
    if ((t & 31) == 0) red[t >> 5] = m;
    __syncthreads();
    if (t == 0) {
        float mm = red[0];
#pragma unroll
        for (int w = 1; w < 8; w++) mm = fmaxf(mm, red[w]);
        g_fdmax[b] = mm;
    }
}

// ---------------------------------------------------------------------------
// Kernel 2: fused gated attention, bf16 m16n8k16 split-split (3 products).
// 512 threads, 16 warps: wg = wid>>3 selects feature half (n-split, scalar
// p work duplicated across groups — no merge); warp-in-group owns 16 q rows.
// ---------------------------------------------------------------------------
#define OFF_HHI 0
#define OFF_HLO 17408
#define OFF_CK  34816
#define OFF_FD  35840
#define BUFSZ   36096
#define SM_TOTAL (2 * BUFSZ)

extern __shared__ char s_raw[];

__device__ __forceinline__ void prefetch_tile(uint32_t sbase, int buf, int b,
                                              int k0, int t,
                                              const float* __restrict__ coord) {
    const uint32_t bb = sbase + buf * BUFSZ;
    const char* hs = (const char*)(g_hb_hi + ((size_t)b * NN + k0) * FOUT);
    const char* ls = (const char*)(g_hb_lo + ((size_t)b * NN + k0) * FOUT);
#pragma unroll
    for (int e = 0; e < 2; e++) {
        int idx = t + e * 512;          // 0..1023
        int r = idx >> 4, c = idx & 15;
        uint32_t doff = (uint32_t)(r * HROW + c * 16);
        uint32_t soff = (uint32_t)(r * 256 + c * 16);
        CP16(bb + OFF_HHI + doff, (const void*)(hs + soff));
        CP16(bb + OFF_HLO + doff, (const void*)(ls + soff));
    }
    if (t < 192) {
        int k = t / 3, c = t - k * 3;
        CP4(bb + OFF_CK + (uint32_t)(k * 4 + c) * 4u,
            (const void*)(coord + ((size_t)b * NN + k0 + k) * 3 + c));
    }
    if (t < KT) {
        CP4(bb + OFF_FD + (uint32_t)t * 4u,
            (const void*)(g_fd + (size_t)b * NN + k0 + t));
    }
}

__device__ __forceinline__ float pcalc(float fs, float M, float cx, float cy,
                                       float cz, float kx, float ky, float kz,
                                       float fd) {
    float dx = cx - kx, dy = cy - ky, dz = cz - kz;
    float d2 = dx * dx + dy * dy + dz * dz;
    float loc = __expf(-CUTOFF * d2);
    float e = fs + fd;
    e = fmaxf(e, ALPHA * e);
    float v = (loc > 0.01f) ? e * loc : NEGINF;
    return __expf(v - M);
}

__global__ __launch_bounds__(512, 1)
void attn_kernel(const float* __restrict__ coord, float* __restrict__ out) {
    const uint32_t sbase = smem_u32(s_raw);
    const int t   = threadIdx.x;
    const int lid = t & 31;
    const int wid = t >> 5;
    const int wg  = wid >> 3;        // feature-half group
    const int wl  = wid & 7;         // warp in group -> q rows
    const int g   = lid >> 2;
    const int t4  = lid & 3;
    const int b   = blockIdx.x >> 4;
    const int q0  = (blockIdx.x & 15) * MT;
    const int row0 = q0 + wl * 16 + g;
    const int row1 = row0 + 8;

    const float fdmax = g_fdmax[b];
    const float fs0 = g_fs[b * NN + row0];
    const float fs1 = g_fs[b * NN + row1];
    const float M0 = fmaxf(0.f, fs0 + fdmax);
    const float M1 = fmaxf(0.f, fs1 + fdmax);
    const float* cp0 = coord + ((size_t)b * NN + row0) * 3;
    const float* cp1 = coord + ((size_t)b * NN + row1) * 3;
    const float c0x = cp0[0], c0y = cp0[1], c0z = cp0[2];
    const float c1x = cp1[0], c1y = cp1[1], c1z = cp1[2];

    const uint32_t loff = (uint32_t)((lid & 15) * HROW + (lid >> 4) * 16);

    float acc[8][4];
#pragma unroll
    for (int nt = 0; nt < 8; nt++)
#pragma unroll
        for (int c = 0; c < 4; c++) acc[nt][c] = 0.f;
    float lsum0 = 0.f, lsum1 = 0.f;

    prefetch_tile(sbase, 0, b, 0, t, coord);
    CP_COMMIT();

    for (int kt = 0; kt < NN / KT; kt++) {
        const int buf = kt & 1;
        __syncthreads();
        if (kt + 1 < NN / KT) {
            prefetch_tile(sbase, buf ^ 1, b, (kt + 1) * KT, t, coord);
            CP_COMMIT();
            CP_WAIT(1);
        } else {
            CP_WAIT(0);
        }
        __syncthreads();

        const float* ckb = (const float*)(s_raw + buf * BUFSZ + OFF_CK);
        const float* fdb = (const float*)(s_raw + buf * BUFSZ + OFF_FD);
        const uint32_t hhi = sbase + buf * BUFSZ + OFF_HHI;
        const uint32_t hlo = sbase + buf * BUFSZ + OFF_HLO;

        // ---- A fragments (both groups compute identical p) ----
        uint32_t ahi[4][4], alo[4][4];
#pragma unroll
        for (int kc = 0; kc < 4; kc++) {
            const int kb = kc * 16 + 2 * t4;
            float pv[2][4];
#pragma unroll
            for (int kk = 0; kk < 4; kk++) {
                int j = kb + (kk >> 1) * 8 + (kk & 1);
                float kx = ckb[j * 4], ky = ckb[j * 4 + 1], kz = ckb[j * 4 + 2];
                float fd = fdb[j];
                pv[0][kk] = pcalc(fs0, M0, c0x, c0y, c0z, kx, ky, kz, fd);
                pv[1][kk] = pcalc(fs1, M1, c1x, c1y, c1z, kx, ky, kz, fd);
            }
            lsum0 += pv[0][0] + pv[0][1] + pv[0][2] + pv[0][3];
            lsum1 += pv[1][0] + pv[1][1] + pv[1][2] + pv[1][3];
#pragma unroll
            for (int rr = 0; rr < 2; rr++) {
#pragma unroll
                for (int hh = 0; hh < 2; hh++) {
                    float pe = pv[rr][hh * 2], po = pv[rr][hh * 2 + 1];
                    uint32_t hp = bfpack(po, pe);
                    float re = pe - __uint_as_float(hp << 16);
                    float ro = po - __uint_as_float(hp & 0xffff0000u);
                    ahi[kc][hh * 2 + rr] = hp;
                    alo[kc][hh * 2 + rr] = bfpack(ro, re);
                }
            }
        }

        // ---- MMA sweep: this group's 4 nt-pairs x 4 kc ----
#pragma unroll
        for (int ntp = 0; ntp < 4; ntp++) {
#pragma unroll
            for (int kc = 0; kc < 4; kc++) {
                uint32_t base = (uint32_t)(kc * 16 * HROW + (wg * 4 + ntp) * 32) + loff;
                uint32_t bh0, bh1, bh2, bh3, bl0, bl1, bl2, bl3;
                LDSM4T(bh0, bh1, bh2, bh3, hhi + base);
                LDSM4T(bl0, bl1, bl2, bl3, hlo + base);
                MMA_BF16(acc[2 * ntp],     ahi[kc], bh0, bh1);
                MMA_BF16(acc[2 * ntp],     ahi[kc], bl0, bl1);
                MMA_BF16(acc[2 * ntp],     alo[kc], bh0, bh1);
                MMA_BF16(acc[2 * ntp + 1], ahi[kc], bh2, bh3);
                MMA_BF16(acc[2 * ntp + 1], ahi[kc], bl2, bl3);
                MMA_BF16(acc[2 * ntp + 1], alo[kc], bh2, bh3);
            }
        }
    }

    // ---- row sums: quad all-reduce over t4 ----
    lsum0 += __shfl_xor_sync(0xffffffffu, lsum0, 1);
    lsum0 += __shfl_xor_sync(0xffffffffu, lsum0, 2);
    lsum1 += __shfl_xor_sync(0xffffffffu, lsum1, 1);
    lsum1 += __shfl_xor_sync(0xffffffffu, lsum1, 2);
    const float inv0 = 1.f / lsum0;
    const float inv1 = 1.f / lsum1;

    // ---- epilogue: normalize, ELU, store this group's feature half ----
    float* o0 = out + ((size_t)b * NN + row0) * FOUT;
    float* o1 = out + ((size_t)b * NN + row1) * FOUT;
#pragma unroll
    for (int nt = 0; nt < 8; nt++) {
        float v0 = acc[nt][0] * inv0, v1 = acc[nt][1] * inv0;
        float v2 = acc[nt][2] * inv1, v3 = acc[nt][3] * inv1;
        v0 = v0 > 0.f ? v0 : (__expf(v0) - 1.f);
        v1 = v1 > 0.f ? v1 : (__expf(v1) - 1.f);
        v2 = v2 > 0.f ? v2 : (__expf(v2) - 1.f);
        v3 = v3 > 0.f ? v3 : (__expf(v3) - 1.f);
        int col = wg * 64 + nt * 8 + 2 * t4;
        *(float2*)(o0 + col) = make_float2(v0, v1);
        *(float2*)(o1 + col) = make_float2(v2, v3);
    }
}

// ---------------------------------------------------------------------------
extern "C" void kernel_launch(void* const* d_in, const int* in_sizes, int n_in,
                              void* d_out, int out_size) {
    const float *x = nullptr, *coord = nullptr, *W = nullptr, *a = nullptr;
    for (int i = 0; i < n_in; i++) {
        switch (in_sizes[i]) {
            case BB * NN * FIN: x     = (const float*)d_in[i]; break;
            case BB * NN * 3:   coord = (const float*)d_in[i]; break;
            case FIN * FOUT:    W     = (const float*)d_in[i]; break;
            case 2 * FOUT:      a     = (const float*)d_in[i]; break;
            default: break;
        }
    }
    float* out = (float*)d_out;

    wsplit_kernel<<<64, 256>>>(W);
    gemm_h_kernel<<<(BB * NN) / 64, 256>>>(x, a);
    fdmax_kernel<<<BB, 256>>>();

    static bool attr_set = false;
    if (!attr_set) {
        cudaFuncSetAttribute(attn_kernel,
                             cudaFuncAttributeMaxDynamicSharedMemorySize, SM_TOTAL);
        attr_set = true;
    }
    attn_kernel<<<BB * (NN / MT), 512, SM_TOTAL>>>(coord, out);
}

// round 16
// speedup vs baseline: 1.3427x; 1.3427x over previous
#include <cuda_runtime.h>
#include <math.h>
#include <stdint.h>

#define BB 8
#define NN 2048
#define FIN 256
#define FOUT 128
#define ALPHA 0.2f
#define NEGINF -9e15f

#define MT 128          // queries per CTA (attn)
#define KT 64           // keys per tile
#define HROW 272        // H/W smem row stride bytes (136 bf16): LDSM conflict-free
#define XROW 80         // x smem row stride bytes (40 bf16): LDSM conflict-free

// log2-domain constants
#define CBF   (-0.14426950408889634f)   // -CUTOFF * log2(e)
#define M2CB  (0.2885390081777927f)     // -2 * CBF
#define TLOG  (-6.643856189774724f)     // log2(0.01)
#define LOG2E (1.4426950408889634f)

// Scratch (no cudaMalloc allowed)
__device__ uint16_t g_hb_hi[BB * NN * FOUT];   // h bf16 hi
__device__ uint16_t g_hb_lo[BB * NN * FOUT];   // h bf16 residual
__device__ uint16_t g_wb_hi[FIN * FOUT];       // W bf16 hi
__device__ uint16_t g_wb_lo[FIN * FOUT];       // W bf16 residual
__device__ float g_fs[BB * NN];
__device__ float g_fd[BB * NN];
__device__ float g_fdmax[BB];
__device__ float g_cbnk[BB * NN];              // CBF * |coord|^2 per node

// ---------------------------------------------------------------------------
// helpers
// ---------------------------------------------------------------------------
__device__ __forceinline__ uint32_t smem_u32(const void* p) {
    uint32_t a;
    asm("{ .reg .u64 t; cvta.to.shared.u64 t, %1; cvt.u32.u64 %0, t; }"
        : "=r"(a) : "l"(p));
    return a;
}
__device__ __forceinline__ uint32_t bfpack(float po, float pe) {
    uint32_t r;
    asm("cvt.rn.bf16x2.f32 %0, %1, %2;" : "=r"(r) : "f"(po), "f"(pe));
    return r;
}
__device__ __forceinline__ float ex2f(float x) {
    float r;
    asm("ex2.approx.f32 %0, %1;" : "=f"(r) : "f"(x));
    return r;
}
#define MMA_BF16(d, a, b0, b1)                                                  \
    asm volatile("mma.sync.aligned.m16n8k16.row.col.f32.bf16.bf16.f32 "         \
                 "{%0,%1,%2,%3},{%4,%5,%6,%7},{%8,%9},{%0,%1,%2,%3};"           \
                 : "+f"((d)[0]), "+f"((d)[1]), "+f"((d)[2]), "+f"((d)[3])       \
                 : "r"((a)[0]), "r"((a)[1]), "r"((a)[2]), "r"((a)[3]),          \
                   "r"(b0), "r"(b1))
#define LDSM4(r0, r1, r2, r3, addr)                                             \
    asm volatile("ldmatrix.sync.aligned.m8n8.x4.shared.b16 "                    \
                 "{%0,%1,%2,%3}, [%4];"                                         \
                 : "=r"(r0), "=r"(r1), "=r"(r2), "=r"(r3) : "r"(addr))
#define LDSM4T(r0, r1, r2, r3, addr)                                            \
    asm volatile("ldmatrix.sync.aligned.m8n8.x4.trans.shared.b16 "              \
                 "{%0,%1,%2,%3}, [%4];"                                         \
                 : "=r"(r0), "=r"(r1), "=r"(r2), "=r"(r3) : "r"(addr))
#define CP16(dst, src) \
    asm volatile("cp.async.cg.shared.global [%0], [%1], 16;" :: "r"(dst), "l"(src))
#define CP4(dst, src) \
    asm volatile("cp.async.ca.shared.global [%0], [%1], 4;" :: "r"(dst), "l"(src))
#define CP_COMMIT() asm volatile("cp.async.commit_group;" ::: "memory")
#define CP_WAIT(n)  asm volatile("cp.async.wait_group %0;" :: "n"(n) : "memory")

// ---------------------------------------------------------------------------
// Kernel 0: split W into bf16 hi/lo
// ---------------------------------------------------------------------------
__global__ void wsplit_kernel(const float* __restrict__ W) {
    int i = blockIdx.x * 256 + threadIdx.x;
    float2 v = ((const float2*)W)[i];
    uint32_t hi = bfpack(v.y, v.x);
    float r0 = v.x - __uint_as_float(hi << 16);
    float r1 = v.y - __uint_as_float(hi & 0xffff0000u);
    ((uint32_t*)g_wb_hi)[i] = hi;
    ((uint32_t*)g_wb_lo)[i] = bfpack(r1, r0);
}

// ---------------------------------------------------------------------------
// Kernel 1: h = x @ W via bf16 split-split MMA (validated R15 version).
// ---------------------------------------------------------------------------
#define GO_XHI 0
#define GO_XLO 5120
#define GO_W   10240
#define GO_PS  45056
#define GO_PD  45568
#define GO_TOT 46080

__global__ __launch_bounds__(256, 2)
void gemm_h_kernel(const float* __restrict__ x, const float* __restrict__ a) {
    __shared__ char sm[GO_TOT];
    const uint32_t sb = smem_u32(sm);

    const int t   = threadIdx.x;
    const int lid = t & 31;
    const int w   = t >> 5;
    const int g   = lid >> 2;
    const int t4  = lid & 3;
    const int row0 = blockIdx.x * 64;
    const int wr  = (w & 3) * 16;
    const int nh  = (w >> 2) * 64;

    {
#pragma unroll
        for (int e = 0; e < 4; e++) {
            int idx = t + e * 256;
            int hl = idx >> 9, rem = idx & 511;
            int r = rem >> 4, c = rem & 15;
            const char* src = (const char*)(hl ? g_wb_lo : g_wb_hi) +
                              (size_t)r * 256 + c * 16;
            CP16(sb + GO_W + hl * 8704 + (uint32_t)(r * HROW + c * 16), src);
        }
        CP_COMMIT();
    }

    float acc[8][4];
#pragma unroll
    for (int nt = 0; nt < 8; nt++)
#pragma unroll
        for (int c = 0; c < 4; c++) acc[nt][c] = 0.f;

    for (int ch = 0; ch < 8; ch++) {
        const int k0 = ch * 32;
        const int buf = ch & 1;

        const int xr = t >> 2, xc = (t & 3) * 8;
        float4 xv0 = ((const float4*)(x + (size_t)(row0 + xr) * FIN + k0 + xc))[0];
        float4 xv1 = ((const float4*)(x + (size_t)(row0 + xr) * FIN + k0 + xc))[1];

        if (ch + 1 < 8) {
#pragma unroll
            for (int e = 0; e < 4; e++) {
                int idx = t + e * 256;
                int hl = idx >> 9, rem = idx & 511;
                int r = rem >> 4, c = rem & 15;
                const char* src = (const char*)(hl ? g_wb_lo : g_wb_hi) +
                                  (size_t)(ch + 1) * 32 * 256 + (size_t)r * 256 + c * 16;
                CP16(sb + GO_W + (buf ^ 1) * 17408 + hl * 8704 +
                     (uint32_t)(r * HROW + c * 16), src);
            }
            CP_COMMIT();
        }

        {
            uint32_t h0 = bfpack(xv0.y, xv0.x), h1 = bfpack(xv0.w, xv0.z);
            uint32_t h2 = bfpack(xv1.y, xv1.x), h3 = bfpack(xv1.w, xv1.z);
            float r0 = xv0.x - __uint_as_float(h0 << 16);
            float r1 = xv0.y - __uint_as_float(h0 & 0xffff0000u);
            float r2 = xv0.z - __uint_as_float(h1 << 16);
            float r3 = xv0.w - __uint_as_float(h1 & 0xffff0000u);
            float r4 = xv1.x - __uint_as_float(h2 << 16);
            float r5 = xv1.y - __uint_as_float(h2 & 0xffff0000u);
            float r6 = xv1.z - __uint_as_float(h3 << 16);
            float r7 = xv1.w - __uint_as_float(h3 & 0xffff0000u);
            uint32_t off = (uint32_t)(xr * XROW + (t & 3) * 16);
            *(uint4*)(sm + GO_XHI + off) = make_uint4(h0, h1, h2, h3);
            *(uint4*)(sm + GO_XLO + off) =
                make_uint4(bfpack(r1, r0), bfpack(r3, r2),
                           bfpack(r5, r4), bfpack(r7, r6));
        }
        if (ch + 1 < 8) { CP_WAIT(1); } else { CP_WAIT(0); }
        __syncthreads();

        const uint32_t xb = sb + (uint32_t)(wr * XROW) +
                            (uint32_t)((lid & 15) * XROW + (lid >> 4) * 16);
        const uint32_t wbh = sb + GO_W + buf * 17408;
#pragma unroll
        for (int kc = 0; kc < 2; kc++) {
            uint32_t ahi[4], alo[4];
            LDSM4(ahi[0], ahi[1], ahi[2], ahi[3], xb + GO_XHI + kc * 32);
            LDSM4(alo[0], alo[1], alo[2], alo[3], xb + GO_XLO + kc * 32);
            uint32_t bbase = wbh + (uint32_t)(kc * 16 * HROW) +
                             (uint32_t)((lid & 15) * HROW + (lid >> 4) * 16);
#pragma unroll
            for (int ntp = 0; ntp < 4; ntp++) {
                uint32_t boff = bbase + (uint32_t)((nh + ntp * 16) * 2);
                uint32_t bh0, bh1, bh2, bh3, bl0, bl1, bl2, bl3;
                LDSM4T(bh0, bh1, bh2, bh3, boff);
                LDSM4T(bl0, bl1, bl2, bl3, boff + 8704);
                MMA_BF16(acc[2 * ntp],     ahi, bh0, bh1);
                MMA_BF16(acc[2 * ntp],     ahi, bl0, bl1);
                MMA_BF16(acc[2 * ntp],     alo, bh0, bh1);
                MMA_BF16(acc[2 * ntp + 1], ahi, bh2, bh3);
                MMA_BF16(acc[2 * ntp + 1], ahi, bl2, bl3);
                MMA_BF16(acc[2 * ntp + 1], alo, bh2, bh3);
            }
        }
        __syncthreads();
    }

    const int rowA = row0 + wr + g;
    const int rowB = rowA + 8;
    float psA = 0.f, pdA = 0.f, psB = 0.f, pdB = 0.f;
#pragma unroll
    for (int nt = 0; nt < 8; nt++) {
        int col = nh + nt * 8 + 2 * t4;
        float c0 = acc[nt][0], c1 = acc[nt][1];
        float c2 = acc[nt][2], c3 = acc[nt][3];
        uint32_t hA = bfpack(c1, c0);
        uint32_t hB = bfpack(c3, c2);
        float rA0 = c0 - __uint_as_float(hA << 16);
        float rA1 = c1 - __uint_as_float(hA & 0xffff0000u);
        float rB0 = c2 - __uint_as_float(hB << 16);
        float rB1 = c3 - __uint_as_float(hB & 0xffff0000u);
        *(uint32_t*)(g_hb_hi + (size_t)rowA * FOUT + col) = hA;
        *(uint32_t*)(g_hb_hi + (size_t)rowB * FOUT + col) = hB;
        *(uint32_t*)(g_hb_lo + (size_t)rowA * FOUT + col) = bfpack(rA1, rA0);
        *(uint32_t*)(g_hb_lo + (size_t)rowB * FOUT + col) = bfpack(rB1, rB0);
        float a0s = __ldg(a + col), a1s = __ldg(a + col + 1);
        float a0d = __ldg(a + FOUT + col), a1d = __ldg(a + FOUT + col + 1);
        psA += c0 * a0s + c1 * a1s;  pdA += c0 * a0d + c1 * a1d;
        psB += c2 * a0s + c3 * a1s;  pdB += c2 * a0d + c3 * a1d;
    }
    psA += __shfl_xor_sync(0xffffffffu, psA, 1);
    psA += __shfl_xor_sync(0xffffffffu, psA, 2);
    pdA += __shfl_xor_sync(0xffffffffu, pdA, 1);
    pdA += __shfl_xor_sync(0xffffffffu, pdA, 2);
    psB += __shfl_xor_sync(0xffffffffu, psB, 1);
    psB += __shfl_xor_sync(0xffffffffu, psB, 2);
    pdB += __shfl_xor_sync(0xffffffffu, pdB, 1);
    pdB += __shfl_xor_sync(0xffffffffu, pdB, 2);
    float* ps = (float*)(sm + GO_PS);
    float* pd = (float*)(sm + GO_PD);
    if (t4 == 0) {
        int half = w >> 2;
        ps[(wr + g) * 2 + half]     = psA;
        ps[(wr + g + 8) * 2 + half] = psB;
        pd[(wr + g) * 2 + half]     = pdA;
        pd[(wr + g + 8) * 2 + half] = pdB;
    }
    __syncthreads();
    if (t < 64) {
        g_fs[row0 + t] = ps[t * 2] + ps[t * 2 + 1];
        g_fd[row0 + t] = pd[t * 2] + pd[t * 2 + 1];
    }
}

// ---------------------------------------------------------------------------
// Kernel 1b: per-batch max of f_dst + fill g_cbnk = CBF*|coord|^2
// ---------------------------------------------------------------------------
__global__ void fdmax_kernel(const float* __restrict__ coord) {
    __shared__ float red[8];
    const int b = blockIdx.x;
    const int t = threadIdx.x;
    float m = -INFINITY;
    for (int j = t; j < NN; j += 256) {
        m = fmaxf(m, g_fd[b * NN + j]);
        const float* cp = coord + ((size_t)b * NN + j) * 3;
        float nx = cp[0], ny = cp[1], nz = cp[2];
        g_cbnk[b * NN + j] = CBF * (nx * nx + ny * ny + nz * nz);
    }
#pragma unroll
    for (int o = 16; o > 0; o >>= 1)
        m = fmaxf(m, __shfl_xor_sync(0xffffffffu, m, o));
    if ((t & 31) == 0) red[t >> 5] = m;
    __syncthreads();
    if (t == 0) {
        float mm = red[0];
#pragma unroll
        for (int w = 1; w < 8; w++) mm = fmaxf(mm, red[w]);
        g_fdmax[b] = mm;
    }
}

// ---------------------------------------------------------------------------
// Kernel 2: fused gated attention, bf16 split-split, KEY-SPLIT across two
// warp groups (16 warps): wg owns keys [32wg,32wg+32) of each tile; scalar
// p work partitioned (not duplicated); epilogue merges acc+lsum via smem.
// ---------------------------------------------------------------------------
#define OFF_HHI 0
#define OFF_HLO 17408
#define OFF_CK  34816
#define OFF_NK  35840
#define BUFSZ   36096
#define SM_TOTAL (2 * BUFSZ)
#define ST_ACC  0          /* staging (post-loop reuse): 8 warps * 8192B */
#define ST_LS   65536      /* lsum staging: 8*128B */

extern __shared__ char s_raw[];

__device__ __forceinline__ void prefetch_tile(uint32_t sbase, int buf, int b,
                                              int k0, int t,
                                              const float* __restrict__ coord) {
    const uint32_t bb = sbase + buf * BUFSZ;
    const char* hs = (const char*)(g_hb_hi + ((size_t)b * NN + k0) * FOUT);
    const char* ls = (const char*)(g_hb_lo + ((size_t)b * NN + k0) * FOUT);
#pragma unroll
    for (int e = 0; e < 2; e++) {
        int idx = t + e * 512;
        int r = idx >> 4, c = idx & 15;
        uint32_t doff = (uint32_t)(r * HROW + c * 16);
        uint32_t soff = (uint32_t)(r * 256 + c * 16);
        CP16(bb + OFF_HHI + doff, (const void*)(hs + soff));
        CP16(bb + OFF_HLO + doff, (const void*)(ls + soff));
    }
    if (t < 192) {                      // coords -> {x,y,z,_} slots
        int k = t / 3, c = t - k * 3;
        CP4(bb + OFF_CK + (uint32_t)(k * 16 + c * 4),
            (const void*)(coord + ((size_t)b * NN + k0 + k) * 3 + c));
    } else if (t < 256) {               // cbnk
        int k = t - 192;
        CP4(bb + OFF_NK + (uint32_t)(k * 4),
            (const void*)(g_cbnk + (size_t)b * NN + k0 + k));
    } else if (t < 320) {               // fd -> .w slot
        int k = t - 256;
        CP4(bb + OFF_CK + (uint32_t)(k * 16 + 12),
            (const void*)(g_fd + (size_t)b * NN + k0 + k));
    }
}

__global__ __launch_bounds__(512, 1)
void attn_kernel(const float* __restrict__ coord, float* __restrict__ out) {
    const uint32_t sbase = smem_u32(s_raw);
    const int t   = threadIdx.x;
    const int lid = t & 31;
    const int wid = t >> 5;
    const int wg  = wid >> 3;        // key-half group
    const int wl  = wid & 7;         // warp-in-group -> q rows
    const int g   = lid >> 2;
    const int t4  = lid & 3;
    const int b   = blockIdx.x >> 4;
    const int q0  = (blockIdx.x & 15) * MT;
    const int row0 = q0 + wl * 16 + g;
    const int row1 = row0 + 8;

    const float fdmax = g_fdmax[b];
    const float fs0 = g_fs[b * NN + row0];
    const float fs1 = g_fs[b * NN + row1];
    const float M0 = fmaxf(0.f, fs0 + fdmax);
    const float M1 = fmaxf(0.f, fs1 + fdmax);
    const float mlog0 = -M0 * LOG2E;
    const float mlog1 = -M1 * LOG2E;
    const float* cp0 = coord + ((size_t)b * NN + row0) * 3;
    const float* cp1 = coord + ((size_t)b * NN + row1) * 3;
    const float c0x = cp0[0], c0y = cp0[1], c0z = cp0[2];
    const float c1x = cp1[0], c1y = cp1[1], c1z = cp1[2];
    const float cbnc0 = CBF * (c0x * c0x + c0y * c0y + c0z * c0z);
    const float cbnc1 = CBF * (c1x * c1x + c1y * c1y + c1z * c1z);

    const uint32_t loff = (uint32_t)((lid & 15) * HROW + (lid >> 4) * 16);

    float acc[16][4];
#pragma unroll
    for (int nt = 0; nt < 16; nt++)
#pragma unroll
        for (int c = 0; c < 4; c++) acc[nt][c] = 0.f;
    float lsum0 = 0.f, lsum1 = 0.f;

    prefetch_tile(sbase, 0, b, 0, t, coord);
    CP_COMMIT();

    for (int kt = 0; kt < NN / KT; kt++) {
        const int buf = kt & 1;
        __syncthreads();
        if (kt + 1 < NN / KT) {
            prefetch_tile(sbase, buf ^ 1, b, (kt + 1) * KT, t, coord);
            CP_COMMIT();
            CP_WAIT(1);
        } else {
            CP_WAIT(0);
        }
        __syncthreads();

        const char* ckb = s_raw + buf * BUFSZ + OFF_CK;
        const char* nkb = s_raw + buf * BUFSZ + OFF_NK;
        const uint32_t hhi = sbase + buf * BUFSZ + OFF_HHI;
        const uint32_t hlo = sbase + buf * BUFSZ + OFF_HLO;

        // ---- A fragments for this group's key half (kc = 2wg+kcl) ----
        uint32_t ahi[2][4], alo[2][4];
#pragma unroll
        for (int kcl = 0; kcl < 2; kcl++) {
            const int kc = wg * 2 + kcl;
            const int kb = kc * 16 + 2 * t4;
            float pv[2][4];
#pragma unroll
            for (int kk = 0; kk < 4; kk++) {
                int j = kb + (kk >> 1) * 8 + (kk & 1);
                float4 k4 = *(const float4*)(ckb + j * 16);   // x,y,z,fd
                float cbnk = *(const float*)(nkb + j * 4);
                // row0
                float s0 = fmaf(c0z, k4.z, fmaf(c0y, k4.y, c0x * k4.x));
                float t0 = fmaf(s0, M2CB, cbnk + cbnc0);
                float loc0 = ex2f(t0);
                float e0 = fs0 + k4.w;
                e0 = fmaxf(e0, ALPHA * e0);
                float v0 = e0 * loc0;
                v0 = (t0 > TLOG) ? v0 : NEGINF;
                float p0 = ex2f(fmaf(v0, LOG2E, mlog0));
                lsum0 += p0;
                pv[0][kk] = p0;
                // row1
                float s1 = fmaf(c1z, k4.z, fmaf(c1y, k4.y, c1x * k4.x));
                float t1 = fmaf(s1, M2CB, cbnk + cbnc1);
                float loc1 = ex2f(t1);
                float e1 = fs1 + k4.w;
                e1 = fmaxf(e1, ALPHA * e1);
                float v1 = e1 * loc1;
                v1 = (t1 > TLOG) ? v1 : NEGINF;
                float p1 = ex2f(fmaf(v1, LOG2E, mlog1));
                lsum1 += p1;
                pv[1][kk] = p1;
            }
#pragma unroll
            for (int rr = 0; rr < 2; rr++) {
#pragma unroll
                for (int hh = 0; hh < 2; hh++) {
                    float pe = pv[rr][hh * 2], po = pv[rr][hh * 2 + 1];
                    uint32_t hp = bfpack(po, pe);
                    float re = pe - __uint_as_float(hp << 16);
                    float ro = po - __uint_as_float(hp & 0xffff0000u);
                    ahi[kcl][hh * 2 + rr] = hp;
                    alo[kcl][hh * 2 + rr] = bfpack(ro, re);
                }
            }
        }

        // ---- MMA sweep over full n, this group's key half ----
#pragma unroll
        for (int ntp = 0; ntp < 8; ntp++) {
#pragma unroll
            for (int kcl = 0; kcl < 2; kcl++) {
                const int kc = wg * 2 + kcl;
                uint32_t base = (uint32_t)(kc * 16 * HROW + ntp * 32) + loff;
                uint32_t bh0, bh1, bh2, bh3, bl0, bl1, bl2, bl3;
                LDSM4T(bh0, bh1, bh2, bh3, hhi + base);
                LDSM4T(bl0, bl1, bl2, bl3, hlo + base);
                MMA_BF16(acc[2 * ntp],     ahi[kcl], bh0, bh1);
                MMA_BF16(acc[2 * ntp],     ahi[kcl], bl0, bl1);
                MMA_BF16(acc[2 * ntp],     alo[kcl], bh0, bh1);
                MMA_BF16(acc[2 * ntp + 1], ahi[kcl], bh2, bh3);
                MMA_BF16(acc[2 * ntp + 1], ahi[kcl], bl2, bl3);
                MMA_BF16(acc[2 * ntp + 1], alo[kcl], bh2, bh3);
            }
        }
    }

    // ---- quad-reduce partial lsums ----
    lsum0 += __shfl_xor_sync(0xffffffffu, lsum0, 1);
    lsum0 += __shfl_xor_sync(0xffffffffu, lsum0, 2);
    lsum1 += __shfl_xor_sync(0xffffffffu, lsum1, 1);
    lsum1 += __shfl_xor_sync(0xffffffffu, lsum1, 2);

    // ---- merge key-halves: wg1 stages, wg0 adds ----
    __syncthreads();   // all MMA reads of smem buffers done
    if (wg == 1) {
        uint32_t sa = sbase + ST_ACC + (uint32_t)(wl * 8192) + (uint32_t)(lid * 16);
#pragma unroll
        for (int nt = 0; nt < 16; nt++) {
            float4 v = make_float4(acc[nt][0], acc[nt][1], acc[nt][2], acc[nt][3]);
            *(float4*)(s_raw + (sa - sbase) + nt * 512) = v;
        }
        if (t4 == 0) {
            *(float*)(s_raw + ST_LS + wl * 128 + g * 8)     = lsum0;
            *(float*)(s_raw + ST_LS + wl * 128 + g * 8 + 4) = lsum1;
        }
    }
    __syncthreads();
    if (wg == 0) {
        uint32_t sa = (uint32_t)(ST_ACC + wl * 8192 + lid * 16);
#pragma unroll
        for (int nt = 0; nt < 16; nt++) {
            float4 v = *(const float4*)(s_raw + sa + nt * 512);
            acc[nt][0] += v.x; acc[nt][1] += v.y;
            acc[nt][2] += v.z; acc[nt][3] += v.w;
        }
        lsum0 += *(const float*)(s_raw + ST_LS + wl * 128 + g * 8);
        lsum1 += *(const float*)(s_raw + ST_LS + wl * 128 + g * 8 + 4);
        const float inv0 = 1.f / lsum0;
        const float inv1 = 1.f / lsum1;

        float* o0 = out + ((size_t)b * NN + row0) * FOUT;
        float* o1 = out + ((size_t)b * NN + row1) * FOUT;
#pragma unroll
        for (int nt = 0; nt < 16; nt++) {
            float v0 = acc[nt][0] * inv0, v1 = acc[nt][1] * inv0;
            float v2 = acc[nt][2] * inv1, v3 = acc[nt][3] * inv1;
            v0 = v0 > 0.f ? v0 : (__expf(v0) - 1.f);
            v1 = v1 > 0.f ? v1 : (__expf(v1) - 1.f);
            v2 = v2 > 0.f ? v2 : (__expf(v2) - 1.f);
            v3 = v3 > 0.f ? v3 : (__expf(v3) - 1.f);
            int col = nt * 8 + 2 * t4;
            *(float2*)(o0 + col) = make_float2(v0, v1);
            *(float2*)(o1 + col) = make_float2(v2, v3);
        }
    }
}

// ---------------------------------------------------------------------------
extern "C" void kernel_launch(void* const* d_in, const int* in_sizes, int n_in,
                              void* d_out, int out_size) {
    const float *x = nullptr, *coord = nullptr, *W = nullptr, *a = nullptr;
    for (int i = 0; i < n_in; i++) {
        switch (in_sizes[i]) {
            case BB * NN * FIN: x     = (const float*)d_in[i]; break;
            case BB * NN * 3:   coord = (const float*)d_in[i]; break;
            case FIN * FOUT:    W     = (const float*)d_in[i]; break;
            case 2 * FOUT:      a     = (const float*)d_in[i]; break;
            default: break;
        }
    }
    float* out = (float*)d_out;

    wsplit_kernel<<<64, 256>>>(W);
    gemm_h_kernel<<<(BB * NN) / 64, 256>>>(x, a);
    fdmax_kernel<<<BB, 256>>>(coord);

    static bool attr_set = false;
    if (!attr_set) {
        cudaFuncSetAttribute(attn_kernel,
                             cudaFuncAttributeMaxDynamicSharedMemorySize, SM_TOTAL);
        attr_set = true;
    }
    attn_kernel<<<BB * (NN / MT), 512, SM_TOTAL>>>(coord, out);
}